// round 8
// baseline (speedup 1.0000x reference)
#include <cuda_runtime.h>
#include <cuda_fp16.h>
#include <cstdint>

#define DT 0.1f
#define TAU_HP 12.3f
#define TAU_LP 2.3f

#define N_NEURONS_MAX 200000
#define N_EDGES_MAX   6400000
#define N_TM1_MAX     25000
#define STEPS_MAX     50

#define CHUNK      51200              // sources per chunk (fits 16-bit local idx)
#define NCHUNK     4                  // ceil(200000/51200)
#define CHUNK_B    (CHUNK * 2)        // bytes per staged fp16 chunk (102400)
#define GRID_STEP  148
#define TPB_STEP   1024
#define GROUPS     256                // 4 lanes per row-group
#define MAX_WAVES  5                  // ceil(ceil(175000/148)/256)

// ---------------- device scratch (no allocations allowed) ----------------
__device__ int      g_counts[NCHUNK * N_NEURONS_MAX];
__device__ int      g_seg_ptr[NCHUNK * N_NEURONS_MAX + 1];
__device__ int      g_cursor[NCHUNK * N_NEURONS_MAX];
__device__ int      g_block_sums[512];
__device__ unsigned g_bar1, g_bar2;
__device__ unsigned g_epk[N_EDGES_MAX];               // packed {w_fp16, src16}
__device__ __align__(16) float  g_vbuf[2][N_NEURONS_MAX];
__device__ __align__(16) __half g_rbuf[2][N_NEURONS_MAX];
__device__ float    g_table[(STEPS_MAX + 1) * N_TM1_MAX];

// ---------------- helpers ----------------
__device__ __forceinline__ uint32_t smem_u32(const void* p) {
    uint32_t a;
    asm("{ .reg .u64 t; cvta.to.shared.u64 t, %1; cvt.u32.u64 %0, t; }"
        : "=r"(a) : "l"(p));
    return a;
}
__device__ __forceinline__ void mbar_init(uint32_t mbar, unsigned cnt) {
    asm volatile("mbarrier.init.shared.b64 [%0], %1;" :: "r"(mbar), "r"(cnt) : "memory");
}
__device__ __forceinline__ void mbar_expect(uint32_t mbar, unsigned bytes) {
    asm volatile("mbarrier.arrive.expect_tx.shared.b64 _, [%0], %1;"
                 :: "r"(mbar), "r"(bytes) : "memory");
}
__device__ __forceinline__ void bulk_cp(uint32_t dst, const void* src,
                                        unsigned bytes, uint32_t mbar) {
    asm volatile("cp.async.bulk.shared::cta.global.mbarrier::complete_tx::bytes "
                 "[%0], [%1], %2, [%3];"
                 :: "r"(dst), "l"(src), "r"(bytes), "r"(mbar) : "memory");
}
__device__ __forceinline__ void mbar_wait(uint32_t mbar, int phase) {
    asm volatile(
        "{\n\t.reg .pred P;\n\t"
        "W%=:\n\t"
        "mbarrier.try_wait.parity.acquire.cta.shared::cta.b64 P, [%0], %1, 0x989680;\n\t"
        "@P bra D%=;\n\t"
        "bra W%=;\n\t"
        "D%=:\n\t}"
        :: "r"(mbar), "r"(phase) : "memory");
}

// ---------------- setup kernels ----------------

__global__ void k_zero(int nseg, int n_neurons) {
    int i = blockIdx.x * blockDim.x + threadIdx.x;
    if (i < nseg) g_counts[i] = 0;
    if (i < n_neurons) { g_vbuf[0][i] = 0.0f; g_rbuf[0][i] = __float2half(0.0f); }
    if (i == 0) { g_bar1 = 0; g_bar2 = 0; }
}

// blocks [0,tb): Tm1 trajectory; rest: per-(target,chunk) histogram
__global__ void k_tm1hist(const float* __restrict__ x,
                          const int* __restrict__ src, const int* __restrict__ tgt,
                          int n_tm1, int steps, int n_edges, int tb) {
    int bid = blockIdx.x;
    if (bid < tb) {
        int i = bid * blockDim.x + threadIdx.x;
        if (i >= n_tm1) return;
        float f = 0.0f, tv = 0.0f;
        for (int s = 0; s < steps; s++) {
            g_table[s * n_tm1 + i] = tv;
            float xi = x[(long long)s * n_tm1 + i];
            float hp = xi - f;
            f  += DT * hp / TAU_HP;
            tv += DT * (fmaxf(hp, 0.0f) - tv) / TAU_LP;
        }
        g_table[steps * n_tm1 + i] = tv;
    } else {
        int e = (bid - tb) * blockDim.x + threadIdx.x;
        if (e >= n_edges) return;
        int t = tgt[e];
        if (t >= n_tm1) {
            int c = src[e] / CHUNK;
            atomicAdd(&g_counts[NCHUNK * t + c], 1);
        }
    }
}

// Fused scan + fill. 4096 elems/block -> 196 blocks, all co-resident (2/SM).
__global__ void __launch_bounds__(1024, 2)
k_scanfill(const int* __restrict__ src, const int* __restrict__ tgt,
           const float* __restrict__ w,
           int n_edges, int n_tm1, int nseg, int nblocks) {
    __shared__ int sh[1024];
    __shared__ int s_off;
    int tid = threadIdx.x, bid = blockIdx.x;

    // phase A: 4 elements per thread
    int base = bid * 4096 + tid * 4;
    int c0 = (base + 0 < nseg) ? g_counts[base + 0] : 0;
    int c1 = (base + 1 < nseg) ? g_counts[base + 1] : 0;
    int c2 = (base + 2 < nseg) ? g_counts[base + 2] : 0;
    int c3 = (base + 3 < nseg) ? g_counts[base + 3] : 0;
    int tot = c0 + c1 + c2 + c3;
    sh[tid] = tot;
    __syncthreads();
    #pragma unroll
    for (int o = 1; o < 1024; o <<= 1) {
        int v = (tid >= o) ? sh[tid - o] : 0;
        __syncthreads();
        sh[tid] += v;
        __syncthreads();
    }
    int incl = sh[tid];
    int excl = incl - tot;
    if (tid == 1023) g_block_sums[bid] = incl;

    __threadfence();
    __syncthreads();
    if (tid == 0) {
        atomicAdd(&g_bar1, 1);
        while (((volatile unsigned*)&g_bar1)[0] < (unsigned)nblocks) {}
        __threadfence();
    }
    __syncthreads();

    if (tid < 32) {
        int p = 0;
        for (int j = tid; j < bid; j += 32) p += g_block_sums[j];
        #pragma unroll
        for (int o = 16; o; o >>= 1) p += __shfl_xor_sync(0xffffffffu, p, o);
        if (tid == 0) s_off = p;
    }
    __syncthreads();
    int off = s_off + excl;
    if (base + 0 < nseg) { g_seg_ptr[base + 0] = off;            g_cursor[base + 0] = off; }
    if (base + 1 < nseg) { g_seg_ptr[base + 1] = off + c0;       g_cursor[base + 1] = off + c0; }
    if (base + 2 < nseg) { g_seg_ptr[base + 2] = off + c0 + c1;  g_cursor[base + 2] = off + c0 + c1; }
    if (base + 3 < nseg) { g_seg_ptr[base + 3] = off + c0 + c1 + c2;
                           g_cursor[base + 3] = off + c0 + c1 + c2; }
    if (bid == nblocks - 1 && tid == 1023) g_seg_ptr[nseg] = s_off + incl;

    __threadfence();
    __syncthreads();
    if (tid == 0) {
        atomicAdd(&g_bar2, 1);
        while (((volatile unsigned*)&g_bar2)[0] < (unsigned)nblocks) {}
        __threadfence();
    }
    __syncthreads();

    // phase C: scatter-fill packed edges
    int gsz = nblocks * 1024;
    for (int e = bid * 1024 + tid; e < n_edges; e += gsz) {
        int tt = tgt[e];
        if (tt >= n_tm1) {
            int s = src[e];
            int c = s / CHUNK;
            int pos = atomicAdd(&g_cursor[NCHUNK * tt + c], 1);
            unsigned short hw = __half_as_ushort(__float2half_rn(w[e]));
            g_epk[pos] = ((unsigned)hw << 16) | (unsigned)(s - c * CHUNK);
        }
    }
}

// ---------------- per-step kernel ----------------
// 148 blocks, 1024 threads. 4 source chunks of 100KB fp16, double-buffered in
// SMEM, staged by cp.async.bulk + mbarrier so staging of chunk c+1 overlaps
// edge processing of chunk c. Edges are 4B packed, L2-resident across steps.
__global__ void __launch_bounds__(TPB_STEP, 1)
k_step(const float*  __restrict__ vold, float* __restrict__ vnew,
       const __half* __restrict__ rold, __half* __restrict__ rnew,
       const float*  __restrict__ table_next,
       const float*  __restrict__ tau, const float* __restrict__ vrest,
       int n_neurons, int n_tm1) {
    extern __shared__ __align__(16) unsigned char smem_raw[];
    __half* sbuf = (__half*)smem_raw;                   // 2 × CHUNK halves
    uint32_t smem_base = smem_u32(smem_raw);
    uint32_t mbar = smem_base + 2 * CHUNK_B;            // 2 mbarriers

    int tid = threadIdx.x, bid = blockIdx.x;
    int group = tid >> 2, lane = tid & 3;

    if (tid == 0) {
        mbar_init(mbar, 1);
        mbar_init(mbar + 8, 1);
        asm volatile("fence.proxy.async.shared::cta;" ::: "memory");
    }
    __syncthreads();

    // kick off chunks 0 and 1
    if (tid == 0) {
        unsigned b0 = (unsigned)min(CHUNK, n_neurons) * 2u;
        mbar_expect(mbar, b0);
        bulk_cp(smem_base, rold, b0, mbar);
    } else if (tid == 32) {
        unsigned b1 = (unsigned)(min(2 * CHUNK, n_neurons) - CHUNK) * 2u;
        mbar_expect(mbar + 8, b1);
        bulk_cp(smem_base + CHUNK_B, rold + CHUNK, b1, mbar + 8);
    }

    // Tm1 refresh overlaps the TMA
    {
        int tper = (n_tm1 + GRID_STEP - 1) / GRID_STEP;
        int t0 = bid * tper, t1 = min(n_tm1, t0 + tper);
        for (int i = t0 + tid; i < t1; i += TPB_STEP) {
            float tv = table_next[i];
            vnew[i] = tv;
            rnew[i] = __float2half(fmaxf(tv, 0.0f));
        }
    }

    int rows = n_neurons - n_tm1;
    int per = (rows + GRID_STEP - 1) / GRID_STEP;
    int r0 = n_tm1 + bid * per;
    int r1 = min(n_neurons, r0 + per);

    float acc[MAX_WAVES];
    #pragma unroll
    for (int w = 0; w < MAX_WAVES; w++) acc[w] = 0.0f;

    #pragma unroll
    for (int c = 0; c < NCHUNK; c++) {
        int b = c & 1;
        mbar_wait(mbar + b * 8, (c >> 1) & 1);
        const __half* sr = sbuf + b * CHUNK;

        #pragma unroll
        for (int w = 0; w < MAX_WAVES; w++) {
            int row = r0 + w * GROUPS + group;
            if (row >= r1) break;
            int s = __ldg(&g_seg_ptr[NCHUNK * row + c]);
            int e = __ldg(&g_seg_ptr[NCHUNK * row + c + 1]);
            float sum = 0.0f;
            int j = s + lane;
            for (; j + 4 < e; j += 8) {
                unsigned u0 = __ldg(&g_epk[j]);
                unsigned u1 = __ldg(&g_epk[j + 4]);
                float rA = __half2float(sr[u0 & 0xFFFFu]);
                float rB = __half2float(sr[u1 & 0xFFFFu]);
                sum += __half2float(__ushort_as_half((unsigned short)(u0 >> 16))) * rA;
                sum += __half2float(__ushort_as_half((unsigned short)(u1 >> 16))) * rB;
            }
            if (j < e) {
                unsigned u = __ldg(&g_epk[j]);
                sum += __half2float(__ushort_as_half((unsigned short)(u >> 16)))
                     * __half2float(sr[u & 0xFFFFu]);
            }
            acc[w] += sum;
        }
        __syncthreads();   // all groups done reading buffer b

        if (c + 2 < NCHUNK && tid == 0) {
            int cs = (c + 2) * CHUNK;
            unsigned bytes = (unsigned)(min(cs + CHUNK, n_neurons) - cs) * 2u;
            mbar_expect(mbar + b * 8, bytes);
            bulk_cp(smem_base + b * CHUNK_B, rold + cs, bytes, mbar + b * 8);
        }
    }

    // finalize rows
    #pragma unroll
    for (int w = 0; w < MAX_WAVES; w++) {
        int row = r0 + w * GROUPS + group;
        if (row >= r1) break;
        float sum = acc[w];
        sum += __shfl_xor_sync(0xffffffffu, sum, 2);
        sum += __shfl_xor_sync(0xffffffffu, sum, 1);
        if (lane == 0) {
            float vv = vold[row];
            float vn = vv + DT * ((sum - vv + vrest[row]) / tau[row]);
            vnew[row] = vn;
            rnew[row] = __float2half(fmaxf(vn, 0.0f));
        }
    }
}

__global__ void k_out(float* __restrict__ out, const float* __restrict__ vfinal,
                      int n, int n_tm1, int steps) {
    int i = blockIdx.x * blockDim.x + threadIdx.x;
    if (i >= n) return;
    out[i] = (i < n_tm1) ? g_table[(steps - 1) * n_tm1 + i] : vfinal[i];
}

// ---------------- launch ----------------

extern "C" void kernel_launch(void* const* d_in, const int* in_sizes, int n_in,
                              void* d_out, int out_size) {
    const float* tm1_input = (const float*)d_in[0];
    const float* weights   = (const float*)d_in[1];
    const float* tau       = (const float*)d_in[2];
    const float* vrest     = (const float*)d_in[3];
    const int*   src       = (const int*)  d_in[4];
    const int*   tgt       = (const int*)  d_in[5];

    const int n_tm1     = 25000;
    const int n_edges   = in_sizes[1];
    const int n_neurons = in_sizes[2];
    const int steps     = in_sizes[0] / n_tm1;

    const int nseg = NCHUNK * n_neurons;
    const int smem_bytes = 2 * CHUNK_B + 32;          // 2 buffers + mbarriers

    cudaFuncSetAttribute(k_step, cudaFuncAttributeMaxDynamicSharedMemorySize, smem_bytes);

    k_zero<<<(nseg + 255) / 256, 256>>>(nseg, n_neurons);
    int tb = (n_tm1 + 255) / 256;
    int eb = (n_edges + 255) / 256;
    k_tm1hist<<<tb + eb, 256>>>(tm1_input, src, tgt, n_tm1, steps, n_edges, tb);
    int scan_blocks = (nseg + 4095) / 4096;           // 196, all co-resident
    k_scanfill<<<scan_blocks, 1024>>>(src, tgt, weights, n_edges, n_tm1,
                                      nseg, scan_blocks);

    float*  vbase = nullptr;
    __half* rbase = nullptr;
    float*  tbl   = nullptr;
    cudaGetSymbolAddress((void**)&vbase, g_vbuf);
    cudaGetSymbolAddress((void**)&rbase, g_rbuf);
    cudaGetSymbolAddress((void**)&tbl,   g_table);

    for (int st = 0; st < steps; st++) {
        const float*  vold = vbase + (size_t)(st & 1) * N_NEURONS_MAX;
        float*        vnew = vbase + (size_t)((st + 1) & 1) * N_NEURONS_MAX;
        const __half* rold = rbase + (size_t)(st & 1) * N_NEURONS_MAX;
        __half*       rnew = rbase + (size_t)((st + 1) & 1) * N_NEURONS_MAX;
        const float*  table_next = tbl + (size_t)(st + 1) * n_tm1;
        k_step<<<GRID_STEP, TPB_STEP, smem_bytes>>>(vold, vnew, rold, rnew,
                                                    table_next, tau, vrest,
                                                    n_neurons, n_tm1);
    }

    const float* vfinal = vbase + (size_t)(steps & 1) * N_NEURONS_MAX;
    k_out<<<(out_size + 255) / 256, 256>>>((float*)d_out, vfinal,
                                           out_size, n_tm1, steps);
}